// round 11
// baseline (speedup 1.0000x reference)
#include <cuda_runtime.h>
#include <cuda_fp16.h>
#include <cstdint>

// ============================================================
// Problem constants
// ============================================================
#define N_NODES 100000
#define H_FEATS 128

// P[node][0:128] = h[node] @ W1[0:128,:]   (src half)
// P[node][128:256] = h[node] @ W1[128:256,:] (dst half)
// Stored fp16: 51.2 MB -> L2-resident, halves edge-gather traffic.
__device__ __align__(16) __half g_Ph[(size_t)N_NODES * 256];
__device__ int g_idx_is64;

// ============================================================
// Helpers
// ============================================================
__device__ __forceinline__ uint32_t smem_u32(const void* p) {
    uint32_t a;
    asm("{ .reg .u64 t; cvta.to.shared.u64 t, %1; cvt.u32.u64 %0, t; }"
        : "=r"(a) : "l"(p));
    return a;
}

// mma.sync m16n8k16 fp16 in, fp32 accum (sm_80 baseline PTX; legal on compute_103)
__device__ __forceinline__ void mma_f16(float* c, const uint32_t* a, const uint32_t* b) {
    asm volatile(
        "mma.sync.aligned.m16n8k16.row.col.f32.f16.f16.f32 "
        "{%0,%1,%2,%3}, {%4,%5,%6,%7}, {%8,%9}, {%0,%1,%2,%3};"
        : "+f"(c[0]), "+f"(c[1]), "+f"(c[2]), "+f"(c[3])
        : "r"(a[0]), "r"(a[1]), "r"(a[2]), "r"(a[3]),
          "r"(b[0]), "r"(b[1]));
}

__device__ __forceinline__ void ldsm_x4(uint32_t* r, uint32_t addr) {
    asm volatile("ldmatrix.sync.aligned.m8n8.x4.shared.b16 {%0,%1,%2,%3}, [%4];"
        : "=r"(r[0]), "=r"(r[1]), "=r"(r[2]), "=r"(r[3]) : "r"(addr));
}
__device__ __forceinline__ void ldsm_x4_trans(uint32_t* r, uint32_t addr) {
    asm volatile("ldmatrix.sync.aligned.m8n8.x4.trans.shared.b16 {%0,%1,%2,%3}, [%4];"
        : "=r"(r[0]), "=r"(r[1]), "=r"(r[2]), "=r"(r[3]) : "r"(addr));
}

__device__ __forceinline__ uint32_t pack_h2(float x, float y) {
    __half2 h = __floats2half2_rn(x, y);
    return *reinterpret_cast<uint32_t*>(&h);
}

// ============================================================
// Kernel A: P[node][half*128:+128] = h[node] @ W1[half*128:+128, :]
// CTA: M=128 nodes, N=128, K=128. 256 threads, 8 warps (4M x 2N),
// warp tile 32x64, fp16 m16n8k16, ldmatrix fragment loads.
// 2 CTAs/SM (69.6KB smem, <=128 regs).
// A: Ap[m][k] halves, row pitch LDAP words (272B -> ldmatrix conflict-free)
// B: Bs[k][n] halves, row pitch LDBH halves (272B)
// ============================================================
#define LDAP 68    // uint32 (half2) per A row: 64 data + 4 pad  (272B pitch)
#define LDBH 136   // halves per B row: 128 data + 8 pad         (272B pitch)
#define LDOW 68    // words per Po row (128 halves + 8 pad halves)
#define SMEM_BYTES (128 * LDAP * 4 + 128 * LDBH * 2)   // 34816 + 34816 = 69632

__global__ void __launch_bounds__(256, 2)
precompute_kernel(const float* __restrict__ h, const float* __restrict__ W1) {
    extern __shared__ uint32_t smw[];
    uint32_t* Ap = smw;                                          // [128][LDAP] half2
    __half* Bs = reinterpret_cast<__half*>(smw + 128 * LDAP);    // [128][LDBH] half
    __half* Po = reinterpret_cast<__half*>(Ap);                  // reuse A region

    const int tid = threadIdx.x;
    const int half = blockIdx.y;
    const long tile_base = (long)blockIdx.x * 128;

    // --- Stage A: h rows fp32 -> packed fp16; one warp per node row ---
    #pragma unroll
    for (int i = tid; i < 128 * 32; i += 256) {
        int r = i >> 5, c4 = i & 31;
        long node = tile_base + r;
        uint2 u = {0u, 0u};
        if (node < N_NODES) {
            float4 v = *reinterpret_cast<const float4*>(h + node * 128 + c4 * 4);
            u.x = pack_h2(v.x, v.y);
            u.y = pack_h2(v.z, v.w);
        }
        *reinterpret_cast<uint2*>(&Ap[r * LDAP + c4 * 2]) = u;
    }
    // --- Stage B: W1[half*128 + k][n] -> Bs[k][n] halves ---
    const float* W1h = W1 + (size_t)half * 128 * 128;
    #pragma unroll
    for (int i = tid; i < 128 * 32; i += 256) {
        int k = i >> 5, c4 = i & 31;
        float4 v = *reinterpret_cast<const float4*>(W1h + k * 128 + c4 * 4);
        uint2 u;
        u.x = pack_h2(v.x, v.y);
        u.y = pack_h2(v.z, v.w);
        *reinterpret_cast<uint2*>(&Bs[k * LDBH + c4 * 4]) = u;
    }
    __syncthreads();

    // --- Compute: 8 warps, 4 along M x 2 along N, warp tile 32x64 ---
    const int wid = tid >> 5, lane = tid & 31;
    const int g = lane >> 2, tg = lane & 3;
    const int wm = wid & 3, wn = wid >> 2;
    const int m0 = wm * 32, n0 = wn * 64;

    const uint32_t Ap_u = smem_u32(Ap);
    const uint32_t Bs_u = smem_u32(Bs);

    // ldmatrix source addresses
    // A (x4): lanes 0-7 -> row m0+l,k0 | 8-15 -> m0+8+l,k0 | 16-23 -> m0+l,k+8 | 24-31 -> m0+8+l,k+8
    uint32_t a_addr[2];
    {
        int r = (lane & 7) + ((lane >> 3) & 1) * 8;
        int kw = ((lane >> 4) & 1) * 4;   // +8 halves = +4 words
        a_addr[0] = Ap_u + (uint32_t)((m0 + r) * LDAP + kw) * 4;
        a_addr[1] = Ap_u + (uint32_t)((m0 + 16 + r) * LDAP + kw) * 4;
    }
    // B (x4.trans): lanes 0-7 -> k0+l,n | 8-15 -> k8+l,n | 16-23 -> k0+l,n+8 | 24-31 -> k8+l,n+8
    uint32_t b_addr[4];
    {
        int kr = (lane & 7) + ((lane >> 3) & 1) * 8;
        int nn = ((lane >> 4) & 1) * 8;
        #pragma unroll
        for (int t = 0; t < 4; t++)
            b_addr[t] = Bs_u + (uint32_t)(kr * LDBH + n0 + t * 16 + nn) * 2;
    }

    float acc[2][8][4];
    #pragma unroll
    for (int mt = 0; mt < 2; mt++)
        #pragma unroll
        for (int nt = 0; nt < 8; nt++)
            #pragma unroll
            for (int j = 0; j < 4; j++)
                acc[mt][nt][j] = 0.0f;

    #pragma unroll
    for (int ks = 0; ks < 8; ks++) {
        const uint32_t a_ofs = (uint32_t)ks * 32;              // 8 words = 16 halves
        const uint32_t b_ofs = (uint32_t)ks * 16 * LDBH * 2;   // 16 k-rows
        uint32_t a[2][4];
        ldsm_x4(a[0], a_addr[0] + a_ofs);
        ldsm_x4(a[1], a_addr[1] + a_ofs);
        uint32_t b[8][2];
        #pragma unroll
        for (int t = 0; t < 4; t++) {
            uint32_t r[4];
            ldsm_x4_trans(r, b_addr[t] + b_ofs);
            b[2 * t][0] = r[0]; b[2 * t][1] = r[1];
            b[2 * t + 1][0] = r[2]; b[2 * t + 1][1] = r[3];
        }
        #pragma unroll
        for (int mt = 0; mt < 2; mt++)
            #pragma unroll
            for (int nt = 0; nt < 8; nt++)
                mma_f16(acc[mt][nt], a[mt], b[nt]);
    }

    __syncthreads();  // all warps done reading Ap before overwrite as Po

    // --- Stage acc -> Po fp16 in smem (conflict-free half2 stores) ---
    #pragma unroll
    for (int mt = 0; mt < 2; mt++) {
        const int row0 = m0 + mt * 16 + g;
        #pragma unroll
        for (int nt = 0; nt < 8; nt++) {
            const int colw = (n0 + nt * 8 + tg * 2) >> 1;  // half2 index in row
            reinterpret_cast<uint32_t*>(Po)[row0 * LDOW + colw] =
                pack_h2(acc[mt][nt][0], acc[mt][nt][1]);
            reinterpret_cast<uint32_t*>(Po)[(row0 + 8) * LDOW + colw] =
                pack_h2(acc[mt][nt][2], acc[mt][nt][3]);
        }
    }
    __syncthreads();

    // --- Coalesced copy-out: 256B per node row into this half's slot ---
    #pragma unroll
    for (int i = tid; i < 128 * 16; i += 256) {
        int r = i >> 4, c = i & 15;
        long node = tile_base + r;
        if (node < N_NODES) {
            uint4 v = *reinterpret_cast<const uint4*>(
                reinterpret_cast<const uint32_t*>(Po) + r * LDOW + c * 4);
            *reinterpret_cast<uint4*>(g_Ph + node * 256 + half * 128 + c * 8) = v;
        }
    }
}

// ============================================================
// Detector: are src/dst int64 (high 32-bit words all zero) or int32?
// ============================================================
__global__ void detect_kernel(const int* __restrict__ src32) {
    if (threadIdx.x == 0) {
        int any = 0;
        #pragma unroll 4
        for (int i = 0; i < 64; i++) any |= src32[2 * i + 1];
        g_idx_is64 = (any == 0) ? 1 : 0;
    }
}

// ============================================================
// Kernel B: 16 lanes per edge, 4 edges per 16-lane group per iter
// (8 edges in flight per warp; 8 outstanding LDG.128 gathers).
// score[e] = b2 + sum_n relu(P[src][n] + P[dst][128+n] + b1[n]) * W2[n]
// ============================================================
__device__ __forceinline__ float edge_partial(
    const uint4& av, const uint4& bv,
    const float4& b1lo, const float4& b1hi,
    const float4& w2lo, const float4& w2hi) {
    const __half2* ah = reinterpret_cast<const __half2*>(&av);
    const __half2* bh = reinterpret_cast<const __half2*>(&bv);
    float2 fa0 = __half22float2(ah[0]), fb0 = __half22float2(bh[0]);
    float2 fa1 = __half22float2(ah[1]), fb1 = __half22float2(bh[1]);
    float2 fa2 = __half22float2(ah[2]), fb2 = __half22float2(bh[2]);
    float2 fa3 = __half22float2(ah[3]), fb3 = __half22float2(bh[3]);
    float x0 = fmaxf(fa0.x + fb0.x + b1lo.x, 0.0f);
    float x1 = fmaxf(fa0.y + fb0.y + b1lo.y, 0.0f);
    float x2 = fmaxf(fa1.x + fb1.x + b1lo.z, 0.0f);
    float x3 = fmaxf(fa1.y + fb1.y + b1lo.w, 0.0f);
    float x4 = fmaxf(fa2.x + fb2.x + b1hi.x, 0.0f);
    float x5 = fmaxf(fa2.y + fb2.y + b1hi.y, 0.0f);
    float x6 = fmaxf(fa3.x + fb3.x + b1hi.z, 0.0f);
    float x7 = fmaxf(fa3.y + fb3.y + b1hi.w, 0.0f);
    return x0 * w2lo.x + x1 * w2lo.y + x2 * w2lo.z + x3 * w2lo.w
         + x4 * w2hi.x + x5 * w2hi.y + x6 * w2hi.z + x7 * w2hi.w;
}

__global__ void __launch_bounds__(256)
edge_kernel(const void* __restrict__ src, const void* __restrict__ dst,
            const float* __restrict__ b1, const float* __restrict__ W2,
            const float* __restrict__ b2, float* __restrict__ out, int E) {
    const int lane = threadIdx.x & 31;
    const int sub = lane >> 4;      // group 0/1 within warp
    const int l16 = lane & 15;
    const int gw = (blockIdx.x * blockDim.x + threadIdx.x) >> 5;
    const int nw = (gridDim.x * blockDim.x) >> 5;
    const int noct = (E + 7) >> 3;  // 8 edges per warp-iter

    const float4 b1lo = reinterpret_cast<const float4*>(b1)[l16 * 2];
    const float4 b1hi = reinterpret_cast<const float4*>(b1)[l16 * 2 + 1];
    const float4 w2lo = reinterpret_cast<const float4*>(W2)[l16 * 2];
    const float4 w2hi = reinterpret_cast<const float4*>(W2)[l16 * 2 + 1];
    const float b2v = b2[0];
    const int is64 = g_idx_is64;
    const long long* src64 = reinterpret_cast<const long long*>(src);
    const long long* dst64 = reinterpret_cast<const long long*>(dst);
    const int* src32 = reinterpret_cast<const int*>(src);
    const int* dst32 = reinterpret_cast<const int*>(dst);

    for (int q = gw; q < noct; q += nw) {
        const int ebase = q * 8 + sub * 4;

        // --- All 8 index loads first ---
        long s[4], d[4];
        #pragma unroll
        for (int j = 0; j < 4; j++) {
            int e = ebase + j;
            if (e < E) {
                if (is64) { s[j] = (long)src64[e]; d[j] = (long)dst64[e]; }
                else      { s[j] = src32[e];       d[j] = dst32[e]; }
            } else { s[j] = 0; d[j] = 0; }
        }

        // --- 8 independent LDG.128 gathers, issued back-to-back ---
        uint4 av[4], bv[4];
        #pragma unroll
        for (int j = 0; j < 4; j++) {
            av[j] = reinterpret_cast<const uint4*>(g_Ph + (size_t)s[j] * 256)[l16];
            bv[j] = reinterpret_cast<const uint4*>(g_Ph + (size_t)d[j] * 256 + 128)[l16];
        }

        // --- Compute partials ---
        float acc[4];
        #pragma unroll
        for (int j = 0; j < 4; j++)
            acc[j] = edge_partial(av[j], bv[j], b1lo, b1hi, w2lo, w2hi);

        // --- Shared reduction tree over 16 lanes for all four edges ---
        #pragma unroll
        for (int m = 8; m > 0; m >>= 1) {
            #pragma unroll
            for (int j = 0; j < 4; j++)
                acc[j] += __shfl_xor_sync(0xFFFFFFFFu, acc[j], m);
        }

        if (l16 == 0) {
            #pragma unroll
            for (int j = 0; j < 4; j++) {
                int e = ebase + j;
                if (e < E) out[e] = acc[j] + b2v;
            }
        }
    }
}

// ============================================================
// Launch
// ============================================================
extern "C" void kernel_launch(void* const* d_in, const int* in_sizes, int n_in,
                              void* d_out, int out_size) {
    const float* h   = (const float*)d_in[0];
    const void*  src = d_in[1];
    const void*  dst = d_in[2];
    const float* W1  = (const float*)d_in[3];
    const float* b1  = (const float*)d_in[4];
    const float* W2  = (const float*)d_in[5];
    const float* b2  = (const float*)d_in[6];
    float* out = (float*)d_out;
    const int E = out_size;  // one score per edge
    (void)in_sizes; (void)n_in;

    cudaFuncSetAttribute(precompute_kernel,
                         cudaFuncAttributeMaxDynamicSharedMemorySize, SMEM_BYTES);

    dim3 grid((N_NODES + 127) / 128, 2);  // 782 x 2 halves
    precompute_kernel<<<grid, 256, SMEM_BYTES>>>(h, W1);
    detect_kernel<<<1, 32>>>((const int*)src);
    edge_kernel<<<2368, 256>>>(src, dst, b1, W2, b2, out, E);
}

// round 12
// speedup vs baseline: 1.0424x; 1.0424x over previous
#include <cuda_runtime.h>
#include <cuda_fp16.h>
#include <cstdint>

// ============================================================
// Problem constants
// ============================================================
#define N_NODES 100000
#define H_FEATS 128

// P[node][0:128] = h[node] @ W1[0:128,:]   (src half)
// P[node][128:256] = h[node] @ W1[128:256,:] (dst half)
// Stored fp16: 51.2 MB -> L2-resident, halves edge-gather traffic.
__device__ __align__(16) __half g_Ph[(size_t)N_NODES * 256];
__device__ int g_idx_is64;

// ============================================================
// Helpers
// ============================================================
// mma.sync m16n8k16 fp16 in, fp32 accum (sm_80 baseline PTX; legal on compute_103)
__device__ __forceinline__ void mma_f16(float* c, const uint32_t* a, const uint32_t* b) {
    asm volatile(
        "mma.sync.aligned.m16n8k16.row.col.f32.f16.f16.f32 "
        "{%0,%1,%2,%3}, {%4,%5,%6,%7}, {%8,%9}, {%0,%1,%2,%3};"
        : "+f"(c[0]), "+f"(c[1]), "+f"(c[2]), "+f"(c[3])
        : "r"(a[0]), "r"(a[1]), "r"(a[2]), "r"(a[3]),
          "r"(b[0]), "r"(b[1]));
}

__device__ __forceinline__ uint32_t pack_h2(float x, float y) {
    __half2 h = __floats2half2_rn(x, y);
    return *reinterpret_cast<uint32_t*>(&h);
}

// ============================================================
// Kernel A: quarter q of P: out cols [q*64, q*64+64).
//   half = q>>1 selects W1 row-block; P col = q*64 + n.
// CTA: M=128 nodes, N=64, K=128. 256 threads, 8 warps (4M x 2N),
// warp tile 32x32, fp16 m16n8k16 scalar-LDS fragments (R10-proven layout).
// 3 CTAs/SM (53KB smem, <=85 regs via launch_bounds).
// A packed: Ap[row][kh] = half2(A[row][2kh], A[row][2kh+1]),  pitch LDAP words
// B packed: Bp[kh][n]  = half2(W[2kh][n],  W[2kh+1][n]),      pitch LDBP words
// ============================================================
#define LDAP 68    // uint32 per A row: 64 data + 4 pad -> bank 4g+tg bijective
#define LDBP 72    // uint32 per B row: 64 data + 8 pad -> bank 8tg+g bijective
#define LDOW 36    // words per Po row: 32 data (64 halves) + 4 pad
#define SMEM_BYTES ((128 * LDAP + 64 * LDBP) * 4)   // 34816 + 18432 = 53248

__global__ void __launch_bounds__(256, 3)
precompute_kernel(const float* __restrict__ h, const float* __restrict__ W1) {
    extern __shared__ uint32_t smw[];
    uint32_t* Ap = smw;                  // [128][LDAP] half2
    uint32_t* Bp = smw + 128 * LDAP;     // [64][LDBP]  half2
    __half* Po = reinterpret_cast<__half*>(Ap);  // reuse A region for epilogue

    const int tid = threadIdx.x;
    const int q = blockIdx.x;            // quarter 0..3
    const int half = q >> 1;
    const int ncol = q & 1;
    const long tile_base = (long)blockIdx.y * 128;

    // --- Stage A: h rows fp32 -> packed fp16 ---
    #pragma unroll
    for (int i = tid; i < 128 * 32; i += 256) {
        int r = i >> 5, c4 = i & 31;
        long node = tile_base + r;
        uint2 u = {0u, 0u};
        if (node < N_NODES) {
            float4 v = *reinterpret_cast<const float4*>(h + node * 128 + c4 * 4);
            u.x = pack_h2(v.x, v.y);
            u.y = pack_h2(v.z, v.w);
        }
        *reinterpret_cast<uint2*>(&Ap[r * LDAP + c4 * 2]) = u;
    }
    // --- Stage B: W1 row-pairs (2r2, 2r2+1) of this half, col slice ncol*64 ---
    const float* W1h = W1 + (size_t)half * 128 * 128 + ncol * 64;
    #pragma unroll
    for (int i = tid; i < 64 * 16; i += 256) {
        int r2 = i >> 4, c4 = i & 15;
        float4 v0 = *reinterpret_cast<const float4*>(W1h + (2 * r2) * 128 + c4 * 4);
        float4 v1 = *reinterpret_cast<const float4*>(W1h + (2 * r2 + 1) * 128 + c4 * 4);
        uint4 u;
        u.x = pack_h2(v0.x, v1.x);
        u.y = pack_h2(v0.y, v1.y);
        u.z = pack_h2(v0.z, v1.z);
        u.w = pack_h2(v0.w, v1.w);
        *reinterpret_cast<uint4*>(&Bp[r2 * LDBP + c4 * 4]) = u;
    }
    __syncthreads();

    // --- Compute: 8 warps, 4 along M x 2 along N, warp tile 32x32 ---
    const int wid = tid >> 5, lane = tid & 31;
    const int g = lane >> 2, tg = lane & 3;
    const int wm = wid & 3, wn = wid >> 2;
    const int m0 = wm * 32, n0 = wn * 32;

    float acc[2][4][4];
    #pragma unroll
    for (int mt = 0; mt < 2; mt++)
        #pragma unroll
        for (int nt = 0; nt < 4; nt++)
            #pragma unroll
            for (int j = 0; j < 4; j++)
                acc[mt][nt][j] = 0.0f;

    #pragma unroll
    for (int ks = 0; ks < 8; ks++) {
        const int k0h = ks * 8;   // half2 index of this k16 block
        uint32_t a[2][4];
        #pragma unroll
        for (int mt = 0; mt < 2; mt++) {
            const int row = m0 + mt * 16 + g;
            a[mt][0] = Ap[row * LDAP + k0h + tg];
            a[mt][1] = Ap[(row + 8) * LDAP + k0h + tg];
            a[mt][2] = Ap[row * LDAP + k0h + tg + 4];
            a[mt][3] = Ap[(row + 8) * LDAP + k0h + tg + 4];
        }
        uint32_t b[4][2];
        #pragma unroll
        for (int nt = 0; nt < 4; nt++) {
            const int col = n0 + nt * 8 + g;
            b[nt][0] = Bp[(k0h + tg) * LDBP + col];
            b[nt][1] = Bp[(k0h + tg + 4) * LDBP + col];
        }
        #pragma unroll
        for (int mt = 0; mt < 2; mt++)
            #pragma unroll
            for (int nt = 0; nt < 4; nt++)
                mma_f16(acc[mt][nt], a[mt], b[nt]);
    }

    __syncthreads();  // all warps done reading Ap before overwrite as Po

    // --- Stage acc -> Po fp16 in smem (conflict-free half2 stores) ---
    #pragma unroll
    for (int mt = 0; mt < 2; mt++) {
        const int row0 = m0 + mt * 16 + g;
        #pragma unroll
        for (int nt = 0; nt < 4; nt++) {
            const int colw = (n0 + nt * 8 + tg * 2) >> 1;  // half2 index in row
            reinterpret_cast<uint32_t*>(Po)[row0 * LDOW + colw] =
                pack_h2(acc[mt][nt][0], acc[mt][nt][1]);
            reinterpret_cast<uint32_t*>(Po)[(row0 + 8) * LDOW + colw] =
                pack_h2(acc[mt][nt][2], acc[mt][nt][3]);
        }
    }
    __syncthreads();

    // --- Coalesced copy-out: 128B per node row into this quarter's slot ---
    #pragma unroll
    for (int i = tid; i < 128 * 8; i += 256) {
        int r = i >> 3, c = i & 7;
        long node = tile_base + r;
        if (node < N_NODES) {
            uint4 v = *reinterpret_cast<const uint4*>(
                reinterpret_cast<const uint32_t*>(Po) + r * LDOW + c * 4);
            *reinterpret_cast<uint4*>(g_Ph + node * 256 + q * 64 + c * 8) = v;
        }
    }
}

// ============================================================
// Detector: are src/dst int64 (high 32-bit words all zero) or int32?
// ============================================================
__global__ void detect_kernel(const int* __restrict__ src32) {
    if (threadIdx.x == 0) {
        int any = 0;
        #pragma unroll 4
        for (int i = 0; i < 64; i++) any |= src32[2 * i + 1];
        g_idx_is64 = (any == 0) ? 1 : 0;
    }
}

// ============================================================
// Kernel B: 16 lanes per edge, 4 edges per 16-lane group per iter
// (8 edges in flight per warp; 8 outstanding LDG.128 gathers).
// score[e] = b2 + sum_n relu(P[src][n] + P[dst][128+n] + b1[n]) * W2[n]
// ============================================================
__device__ __forceinline__ float edge_partial(
    const uint4& av, const uint4& bv,
    const float4& b1lo, const float4& b1hi,
    const float4& w2lo, const float4& w2hi) {
    const __half2* ah = reinterpret_cast<const __half2*>(&av);
    const __half2* bh = reinterpret_cast<const __half2*>(&bv);
    float2 fa0 = __half22float2(ah[0]), fb0 = __half22float2(bh[0]);
    float2 fa1 = __half22float2(ah[1]), fb1 = __half22float2(bh[1]);
    float2 fa2 = __half22float2(ah[2]), fb2 = __half22float2(bh[2]);
    float2 fa3 = __half22float2(ah[3]), fb3 = __half22float2(bh[3]);
    float x0 = fmaxf(fa0.x + fb0.x + b1lo.x, 0.0f);
    float x1 = fmaxf(fa0.y + fb0.y + b1lo.y, 0.0f);
    float x2 = fmaxf(fa1.x + fb1.x + b1lo.z, 0.0f);
    float x3 = fmaxf(fa1.y + fb1.y + b1lo.w, 0.0f);
    float x4 = fmaxf(fa2.x + fb2.x + b1hi.x, 0.0f);
    float x5 = fmaxf(fa2.y + fb2.y + b1hi.y, 0.0f);
    float x6 = fmaxf(fa3.x + fb3.x + b1hi.z, 0.0f);
    float x7 = fmaxf(fa3.y + fb3.y + b1hi.w, 0.0f);
    return x0 * w2lo.x + x1 * w2lo.y + x2 * w2lo.z + x3 * w2lo.w
         + x4 * w2hi.x + x5 * w2hi.y + x6 * w2hi.z + x7 * w2hi.w;
}

__global__ void __launch_bounds__(256)
edge_kernel(const void* __restrict__ src, const void* __restrict__ dst,
            const float* __restrict__ b1, const float* __restrict__ W2,
            const float* __restrict__ b2, float* __restrict__ out, int E) {
    const int lane = threadIdx.x & 31;
    const int sub = lane >> 4;      // group 0/1 within warp
    const int l16 = lane & 15;
    const int gw = (blockIdx.x * blockDim.x + threadIdx.x) >> 5;
    const int nw = (gridDim.x * blockDim.x) >> 5;
    const int noct = (E + 7) >> 3;  // 8 edges per warp-iter

    const float4 b1lo = reinterpret_cast<const float4*>(b1)[l16 * 2];
    const float4 b1hi = reinterpret_cast<const float4*>(b1)[l16 * 2 + 1];
    const float4 w2lo = reinterpret_cast<const float4*>(W2)[l16 * 2];
    const float4 w2hi = reinterpret_cast<const float4*>(W2)[l16 * 2 + 1];
    const float b2v = b2[0];
    const int is64 = g_idx_is64;
    const long long* src64 = reinterpret_cast<const long long*>(src);
    const long long* dst64 = reinterpret_cast<const long long*>(dst);
    const int* src32 = reinterpret_cast<const int*>(src);
    const int* dst32 = reinterpret_cast<const int*>(dst);

    for (int q = gw; q < noct; q += nw) {
        const int ebase = q * 8 + sub * 4;

        // --- All 8 index loads first ---
        long s[4], d[4];
        #pragma unroll
        for (int j = 0; j < 4; j++) {
            int e = ebase + j;
            if (e < E) {
                if (is64) { s[j] = (long)src64[e]; d[j] = (long)dst64[e]; }
                else      { s[j] = src32[e];       d[j] = dst32[e]; }
            } else { s[j] = 0; d[j] = 0; }
        }

        // --- 8 independent LDG.128 gathers, issued back-to-back ---
        uint4 av[4], bv[4];
        #pragma unroll
        for (int j = 0; j < 4; j++) {
            av[j] = reinterpret_cast<const uint4*>(g_Ph + (size_t)s[j] * 256)[l16];
            bv[j] = reinterpret_cast<const uint4*>(g_Ph + (size_t)d[j] * 256 + 128)[l16];
        }

        // --- Compute partials ---
        float acc[4];
        #pragma unroll
        for (int j = 0; j < 4; j++)
            acc[j] = edge_partial(av[j], bv[j], b1lo, b1hi, w2lo, w2hi);

        // --- Shared reduction tree over 16 lanes for all four edges ---
        #pragma unroll
        for (int m = 8; m > 0; m >>= 1) {
            #pragma unroll
            for (int j = 0; j < 4; j++)
                acc[j] += __shfl_xor_sync(0xFFFFFFFFu, acc[j], m);
        }

        if (l16 == 0) {
            #pragma unroll
            for (int j = 0; j < 4; j++) {
                int e = ebase + j;
                if (e < E) out[e] = acc[j] + b2v;
            }
        }
    }
}

// ============================================================
// Launch
// ============================================================
extern "C" void kernel_launch(void* const* d_in, const int* in_sizes, int n_in,
                              void* d_out, int out_size) {
    const float* h   = (const float*)d_in[0];
    const void*  src = d_in[1];
    const void*  dst = d_in[2];
    const float* W1  = (const float*)d_in[3];
    const float* b1  = (const float*)d_in[4];
    const float* W2  = (const float*)d_in[5];
    const float* b2  = (const float*)d_in[6];
    float* out = (float*)d_out;
    const int E = out_size;  // one score per edge
    (void)in_sizes; (void)n_in;

    cudaFuncSetAttribute(precompute_kernel,
                         cudaFuncAttributeMaxDynamicSharedMemorySize, SMEM_BYTES);

    // x = quarter (fastest) so the 4 CTAs sharing one h tile run adjacently.
    dim3 grid(4, (N_NODES + 127) / 128);  // 4 x 782
    precompute_kernel<<<grid, 256, SMEM_BYTES>>>(h, W1);
    detect_kernel<<<1, 32>>>((const int*)src);
    edge_kernel<<<2368, 256>>>(src, dst, b1, W2, b2, out, E);
}

// round 14
// speedup vs baseline: 1.1405x; 1.0941x over previous
#include <cuda_runtime.h>
#include <cuda_fp16.h>
#include <cstdint>

// ============================================================
// Problem constants
// ============================================================
#define N_NODES 100000
#define H_FEATS 128
#define N_TILES 782          // ceil(100000 / 128)
#define PGRID 152            // persistent grid (GB300: 152 SMs)

// P[node][0:128] = h[node] @ W1[0:128,:]   (src half)
// P[node][128:256] = h[node] @ W1[128:256,:] (dst half)
// Stored fp16: 51.2 MB -> L2-resident, halves edge-gather traffic.
__device__ __align__(16) __half g_Ph[(size_t)N_NODES * 256];
__device__ int g_idx_is64;

// ============================================================
// Helpers
// ============================================================
__device__ __forceinline__ uint32_t smem_u32(const void* p) {
    uint32_t a;
    asm("{ .reg .u64 t; cvta.to.shared.u64 t, %1; cvt.u32.u64 %0, t; }"
        : "=r"(a) : "l"(p));
    return a;
}

// mma.sync m16n8k16 fp16 in, fp32 accum (sm_80 baseline PTX; legal on compute_103)
__device__ __forceinline__ void mma_f16(float* c, const uint32_t* a, const uint32_t* b) {
    asm volatile(
        "mma.sync.aligned.m16n8k16.row.col.f32.f16.f16.f32 "
        "{%0,%1,%2,%3}, {%4,%5,%6,%7}, {%8,%9}, {%0,%1,%2,%3};"
        : "+f"(c[0]), "+f"(c[1]), "+f"(c[2]), "+f"(c[3])
        : "r"(a[0]), "r"(a[1]), "r"(a[2]), "r"(a[3]),
          "r"(b[0]), "r"(b[1]));
}

__device__ __forceinline__ uint32_t pack_h2(float x, float y) {
    __half2 h = __floats2half2_rn(x, y);
    return *reinterpret_cast<uint32_t*>(&h);
}

// 16B async copy (L2 -> smem, bypasses L1/RF); src_bytes 0 => zero-fill
__device__ __forceinline__ void cp_async16(uint32_t dst_smem, const void* src, int src_bytes) {
    asm volatile("cp.async.cg.shared.global [%0], [%1], 16, %2;"
                 :: "r"(dst_smem), "l"(src), "r"(src_bytes) : "memory");
}
__device__ __forceinline__ void cp_async_commit() {
    asm volatile("cp.async.commit_group;" ::: "memory");
}
__device__ __forceinline__ void cp_async_wait0() {
    asm volatile("cp.async.wait_group 0;" ::: "memory");
}

// ============================================================
// Kernel A (persistent): P[node][0:256] = h[node] @ [W1a | W1b].
// grid = PGRID, 512 threads, 16 warps (4M x 4N), warp tile 32x64.
// B (all of W1, packed fp16) staged ONCE per CTA; A (fp32) double-buffered
// via cp.async with one-tile lookahead; fp16 pack inline in mainloop.
// Epilogue reuses the just-consumed A buffer.
//
// A buffer: Af[row][k] fp32, pitch LDAF=136 floats (LDS.64 banks 4g+tg,
//   bijective -> conflict-free).
// B: Bp[kh][n] = half2(W1[(n>>7)*128+2kh][n&127], ...2kh+1...), pitch
//   LDBP=264 words (264%32=8 -> banks 8tg+g, conflict-free).
// Epilogue Po: pitch LDOW=132 words (banks 4g+tg, conflict-free).
// ============================================================
#define LDAF 136   // floats per Af row
#define LDBP 264   // words per Bp row
#define LDOW 132   // words per Po row
#define AF_WORDS (128 * LDAF)                       // 17408 floats = 69632 B
#define SMEM_BYTES (2 * AF_WORDS * 4 + 64 * LDBP * 4)  // 139264 + 67584 = 206848

__global__ void __launch_bounds__(512, 1)
precompute_kernel(const float* __restrict__ h, const float* __restrict__ W1) {
    extern __shared__ float smf[];
    float* Af0 = smf;
    float* Af1 = smf + AF_WORDS;
    uint32_t* Bp = reinterpret_cast<uint32_t*>(smf + 2 * AF_WORDS);

    const int tid = threadIdx.x;
    const uint32_t Af_u[2] = { smem_u32(Af0), smem_u32(Af1) };
    float* const Af[2] = { Af0, Af1 };

    // --- Prologue: issue cp.async for tile t0 into buf0 ---
    {
        long base = (long)blockIdx.x * 128;
        #pragma unroll
        for (int i = tid; i < 128 * 32; i += 512) {
            int r = i >> 5, c4 = i & 31;
            long node = base + r;
            int sz = (node < N_NODES) ? 16 : 0;
            cp_async16(Af_u[0] + (uint32_t)(r * LDAF + c4 * 4) * 4,
                       h + node * 128 + c4 * 4, sz);
        }
        cp_async_commit();
    }

    // --- Stage B once: both W1 halves, ALL 128 cols per half, packed fp16 ---
    // i over 2 halves x 64 row-pairs x 32 col-quads = 4096
    #pragma unroll
    for (int i = tid; i < 2 * 64 * 32; i += 512) {
        int hh = i >> 11;            // half 0/1
        int r2 = (i >> 5) & 63;      // k row-pair
        int c4 = i & 31;             // column quad (4 cols) -> covers n 0..127
        const float* Wr = W1 + (size_t)(hh * 128 + 2 * r2) * 128 + c4 * 4;
        float4 v0 = *reinterpret_cast<const float4*>(Wr);
        float4 v1 = *reinterpret_cast<const float4*>(Wr + 128);
        uint4 u;
        u.x = pack_h2(v0.x, v1.x);
        u.y = pack_h2(v0.y, v1.y);
        u.z = pack_h2(v0.z, v1.z);
        u.w = pack_h2(v0.w, v1.w);
        *reinterpret_cast<uint4*>(&Bp[r2 * LDBP + hh * 128 + c4 * 4]) = u;
    }
    cp_async_wait0();
    __syncthreads();

    // --- Warp layout: 16 warps = 4 (M) x 4 (N), warp tile 32x64 ---
    const int wid = tid >> 5, lane = tid & 31;
    const int g = lane >> 2, tg = lane & 3;
    const int wm = wid & 3, wn = wid >> 2;
    const int m0 = wm * 32, n0 = wn * 64;

    int cur = 0;
    for (int t = blockIdx.x; t < N_TILES; t += PGRID, cur ^= 1) {
        // --- Prefetch tile t+PGRID into the other buffer ---
        int tn = t + PGRID;
        if (tn < N_TILES) {
            long base = (long)tn * 128;
            #pragma unroll
            for (int i = tid; i < 128 * 32; i += 512) {
                int r = i >> 5, c4 = i & 31;
                long node = base + r;
                int sz = (node < N_NODES) ? 16 : 0;
                cp_async16(Af_u[cur ^ 1] + (uint32_t)(r * LDAF + c4 * 4) * 4,
                           h + node * 128 + c4 * 4, sz);
            }
        }
        cp_async_commit();

        // --- Mainloop on Af[cur]: LDS.64 fp32 pairs, pack, MMA ---
        const float* A = Af[cur];
        float acc[2][8][4];
        #pragma unroll
        for (int mt = 0; mt < 2; mt++)
            #pragma unroll
            for (int nt = 0; nt < 8; nt++)
                #pragma unroll
                for (int j = 0; j < 4; j++)
                    acc[mt][nt][j] = 0.0f;

        #pragma unroll
        for (int ks = 0; ks < 8; ks++) {
            const int k2 = ks * 16 + 2 * tg;   // float index of this lane's k-pair
            uint32_t a[2][4];
            #pragma unroll
            for (int mt = 0; mt < 2; mt++) {
                const int row = m0 + mt * 16 + g;
                float2 f0 = *reinterpret_cast<const float2*>(&A[row * LDAF + k2]);
                float2 f1 = *reinterpret_cast<const float2*>(&A[(row + 8) * LDAF + k2]);
                float2 f2 = *reinterpret_cast<const float2*>(&A[row * LDAF + k2 + 8]);
                float2 f3 = *reinterpret_cast<const float2*>(&A[(row + 8) * LDAF + k2 + 8]);
                a[mt][0] = pack_h2(f0.x, f0.y);
                a[mt][1] = pack_h2(f1.x, f1.y);
                a[mt][2] = pack_h2(f2.x, f2.y);
                a[mt][3] = pack_h2(f3.x, f3.y);
            }
            uint32_t b[8][2];
            #pragma unroll
            for (int nt = 0; nt < 8; nt++) {
                const int col = n0 + nt * 8 + g;
                b[nt][0] = Bp[(ks * 8 + tg) * LDBP + col];
                b[nt][1] = Bp[(ks * 8 + tg + 4) * LDBP + col];
            }
            #pragma unroll
            for (int mt = 0; mt < 2; mt++)
                #pragma unroll
                for (int nt = 0; nt < 8; nt++)
                    mma_f16(acc[mt][nt], a[mt], b[nt]);
        }

        __syncthreads();  // all warps done reading Af[cur]

        // --- Epilogue: acc -> fp16 into (freed) Af[cur], then copy out ---
        uint32_t* Pw = reinterpret_cast<uint32_t*>(Af[cur]);
        #pragma unroll
        for (int mt = 0; mt < 2; mt++) {
            const int row0 = m0 + mt * 16 + g;
            #pragma unroll
            for (int nt = 0; nt < 8; nt++) {
                const int colw = (n0 + nt * 8 + tg * 2) >> 1;
                Pw[row0 * LDOW + colw] = pack_h2(acc[mt][nt][0], acc[mt][nt][1]);
                Pw[(row0 + 8) * LDOW + colw] = pack_h2(acc[mt][nt][2], acc[mt][nt][3]);
            }
        }
        __syncthreads();

        const long tbase = (long)t * 128;
        #pragma unroll
        for (int i = tid; i < 128 * 32; i += 512) {
            int r = i >> 5, c = i & 31;
            long node = tbase + r;
            if (node < N_NODES) {
                uint4 v = *reinterpret_cast<const uint4*>(&Pw[r * LDOW + c * 4]);
                *reinterpret_cast<uint4*>(g_Ph + node * 256 + c * 8) = v;
            }
        }

        cp_async_wait0();   // tile t+PGRID landed
        __syncthreads();
    }
}

// ============================================================
// Detector: are src/dst int64 (high 32-bit words all zero) or int32?
// ============================================================
__global__ void detect_kernel(const int* __restrict__ src32) {
    if (threadIdx.x == 0) {
        int any = 0;
        #pragma unroll 4
        for (int i = 0; i < 64; i++) any |= src32[2 * i + 1];
        g_idx_is64 = (any == 0) ? 1 : 0;
    }
}

// ============================================================
// Kernel B: 16 lanes per edge, 4 edges per 16-lane group per iter
// (8 edges in flight per warp; 8 outstanding LDG.128 gathers).
// score[e] = b2 + sum_n relu(P[src][n] + P[dst][128+n] + b1[n]) * W2[n]
// ============================================================
__device__ __forceinline__ float edge_partial(
    const uint4& av, const uint4& bv,
    const float4& b1lo, const float4& b1hi,
    const float4& w2lo, const float4& w2hi) {
    const __half2* ah = reinterpret_cast<const __half2*>(&av);
    const __half2* bh = reinterpret_cast<const __half2*>(&bv);
    float2 fa0 = __half22float2(ah[0]), fb0 = __half22float2(bh[0]);
    float2 fa1 = __half22float2(ah[1]), fb1 = __half22float2(bh[1]);
    float2 fa2 = __half22float2(ah[2]), fb2 = __half22float2(bh[2]);
    float2 fa3 = __half22float2(ah[3]), fb3 = __half22float2(bh[3]);
    float x0 = fmaxf(fa0.x + fb0.x + b1lo.x, 0.0f);
    float x1 = fmaxf(fa0.y + fb0.y + b1lo.y, 0.0f);
    float x2 = fmaxf(fa1.x + fb1.x + b1lo.z, 0.0f);
    float x3 = fmaxf(fa1.y + fb1.y + b1lo.w, 0.0f);
    float x4 = fmaxf(fa2.x + fb2.x + b1hi.x, 0.0f);
    float x5 = fmaxf(fa2.y + fb2.y + b1hi.y, 0.0f);
    float x6 = fmaxf(fa3.x + fb3.x + b1hi.z, 0.0f);
    float x7 = fmaxf(fa3.y + fb3.y + b1hi.w, 0.0f);
    return x0 * w2lo.x + x1 * w2lo.y + x2 * w2lo.z + x3 * w2lo.w
         + x4 * w2hi.x + x5 * w2hi.y + x6 * w2hi.z + x7 * w2hi.w;
}

__global__ void __launch_bounds__(256)
edge_kernel(const void* __restrict__ src, const void* __restrict__ dst,
            const float* __restrict__ b1, const float* __restrict__ W2,
            const float* __restrict__ b2, float* __restrict__ out, int E) {
    const int lane = threadIdx.x & 31;
    const int sub = lane >> 4;      // group 0/1 within warp
    const int l16 = lane & 15;
    const int gw = (blockIdx.x * blockDim.x + threadIdx.x) >> 5;
    const int nw = (gridDim.x * blockDim.x) >> 5;
    const int noct = (E + 7) >> 3;  // 8 edges per warp-iter

    const float4 b1lo = reinterpret_cast<const float4*>(b1)[l16 * 2];
    const float4 b1hi = reinterpret_cast<const float4*>(b1)[l16 * 2 + 1];
    const float4 w2lo = reinterpret_cast<const float4*>(W2)[l16 * 2];
    const float4 w2hi = reinterpret_cast<const float4*>(W2)[l16 * 2 + 1];
    const float b2v = b2[0];
    const int is64 = g_idx_is64;
    const long long* src64 = reinterpret_cast<const long long*>(src);
    const long long* dst64 = reinterpret_cast<const long long*>(dst);
    const int* src32 = reinterpret_cast<const int*>(src);
    const int* dst32 = reinterpret_cast<const int*>(dst);

    for (int q = gw; q < noct; q += nw) {
        const int ebase = q * 8 + sub * 4;

        // --- All 8 index loads first ---
        long s[4], d[4];
        #pragma unroll
        for (int j = 0; j < 4; j++) {
            int e = ebase + j;
            if (e < E) {
                if (is64) { s[j] = (long)src64[e]; d[j] = (long)dst64[e]; }
                else      { s[j] = src32[e];       d[j] = dst32[e]; }
            } else { s[j] = 0; d[j] = 0; }
        }

        // --- 8 independent LDG.128 gathers, issued back-to-back ---
        uint4 av[4], bv[4];
        #pragma unroll
        for (int j = 0; j < 4; j++) {
            av[j] = reinterpret_cast<const uint4*>(g_Ph + (size_t)s[j] * 256)[l16];
            bv[j] = reinterpret_cast<const uint4*>(g_Ph + (size_t)d[j] * 256 + 128)[l16];
        }

        // --- Compute partials ---
        float acc[4];
        #pragma unroll
        for (int j = 0; j < 4; j++)
            acc[j] = edge_partial(av[j], bv[j], b1lo, b1hi, w2lo, w2hi);

        // --- Shared reduction tree over 16 lanes for all four edges ---
        #pragma unroll
        for (int m = 8; m > 0; m >>= 1) {
            #pragma unroll
            for (int j = 0; j < 4; j++)
                acc[j] += __shfl_xor_sync(0xFFFFFFFFu, acc[j], m);
        }

        if (l16 == 0) {
            #pragma unroll
            for (int j = 0; j < 4; j++) {
                int e = ebase + j;
                if (e < E) out[e] = acc[j] + b2v;
            }
        }
    }
}

// ============================================================
// Launch
// ============================================================
extern "C" void kernel_launch(void* const* d_in, const int* in_sizes, int n_in,
                              void* d_out, int out_size) {
    const float* h   = (const float*)d_in[0];
    const void*  src = d_in[1];
    const void*  dst = d_in[2];
    const float* W1  = (const float*)d_in[3];
    const float* b1  = (const float*)d_in[4];
    const float* W2  = (const float*)d_in[5];
    const float* b2  = (const float*)d_in[6];
    float* out = (float*)d_out;
    const int E = out_size;  // one score per edge
    (void)in_sizes; (void)n_in;

    cudaFuncSetAttribute(precompute_kernel,
                         cudaFuncAttributeMaxDynamicSharedMemorySize, SMEM_BYTES);

    precompute_kernel<<<PGRID, 512, SMEM_BYTES>>>(h, W1);
    detect_kernel<<<1, 32>>>((const int*)src);
    edge_kernel<<<2368, 256>>>(src, dst, b1, W2, b2, out, E);
}